// round 5
// baseline (speedup 1.0000x reference)
#include <cuda_runtime.h>
#include <cstddef>

// ---------------- problem constants ----------------
#define BB 64
#define TT 512
#define NN 80
#define HT 512
#define HV 1024
#define HI 512
#define G4 2048      // 4*HI
#define KU 1024      // HT + HI

#define GRID   128   // persistent blocks (<=148 SMs -> co-resident)
#define TPB    256
#define KSPLIT 16    // stage-A split-K partials

// ---------------- scratch layout ----------------
constexpr size_t SZ_SPROJ = (size_t)BB * NN * HI;       // 2.62M
constexpr size_t SZ_VPROJ = (size_t)BB * TT * HI;       // 16.8M
constexpr size_t SZ_XGV   = (size_t)BB * TT * G4;       // 67.1M
constexpr size_t SZ_WRE   = (size_t)G4 * KU;            // 2.1M
constexpr size_t SZ_BIASG = G4;
constexpr size_t SZ_UH    = (size_t)BB * HT;            // H_t_s part
constexpr size_t SZ_HB    = (size_t)2 * BB * HI;        // h ping-pong
constexpr size_t SZ_CB    = (size_t)BB * HI;
constexpr size_t SZ_XP    = (size_t)KSPLIT * BB * HI;   // 512K
constexpr size_t SZ_BETA  = (size_t)NN * BB;

constexpr size_t OFF_SPROJ = 0;
constexpr size_t OFF_VPROJ = OFF_SPROJ + SZ_SPROJ;
constexpr size_t OFF_XGV   = OFF_VPROJ + SZ_VPROJ;
constexpr size_t OFF_WRE   = OFF_XGV   + SZ_XGV;
constexpr size_t OFF_BIASG = OFF_WRE   + SZ_WRE;
constexpr size_t OFF_UH    = OFF_BIASG + SZ_BIASG;
constexpr size_t OFF_HB    = OFF_UH    + SZ_UH;
constexpr size_t OFF_CB    = OFF_HB    + SZ_HB;
constexpr size_t OFF_XP    = OFF_CB    + SZ_CB;
constexpr size_t OFF_BETA  = OFF_XP    + SZ_XP;
constexpr size_t SZ_TOTAL  = OFF_BETA  + SZ_BETA;

__device__ float    g_scratch[SZ_TOTAL];
__device__ unsigned g_arrive = 0;
__device__ unsigned g_gen    = 0;

// ---------------- fast activations ----------------
__device__ __forceinline__ float fast_tanh(float x) {
    float e = __expf(2.f * x);
    return 1.f - 2.f / (e + 1.f);          // saturates correctly at +/-1
}
__device__ __forceinline__ float fast_sig(float x) {
    return 1.f / (1.f + __expf(-x));
}

// ---------------- software grid barrier (all GRID blocks resident) ----------------
__device__ __forceinline__ void grid_sync() {
    __syncthreads();
    if (threadIdx.x == 0) {
        __threadfence();
        volatile unsigned* vg = &g_gen;
        unsigned gen = *vg;                 // read BEFORE arriving
        if (atomicAdd(&g_arrive, 1u) == GRID - 1) {
            g_arrive = 0u;
            __threadfence();
            atomicAdd(&g_gen, 1u);
        } else {
            while (*vg == gen) { }
        }
        __threadfence();
    }
    __syncthreads();
}

// ---------------- generic tiled SGEMM: C = A[M,K] * W[N,K]^T (+bias) ----------------
#define BM 64
#define BN 64
#define BKK 16

__global__ __launch_bounds__(256) void gemm_wt(
    const float* __restrict__ A, int lda,
    const float* __restrict__ W, int ldw,
    const float* __restrict__ bias,
    float* __restrict__ C,
    int M, int N, int K)
{
    const int bn0 = blockIdx.x * BN;
    const int bm0 = blockIdx.y * BM;

    __shared__ float As[BKK][BM + 4];
    __shared__ float Ws[BKK][BN + 4];

    const int tid  = threadIdx.x;
    const int tx   = tid & 15;
    const int ty   = tid >> 4;
    const int lrow = tid >> 2;
    const int lkq  = (tid & 3) * 4;

    float acc[4][4];
#pragma unroll
    for (int i = 0; i < 4; i++)
#pragma unroll
        for (int j = 0; j < 4; j++) acc[i][j] = 0.f;

    const float* Ag = A + (size_t)(bm0 + lrow) * lda + lkq;
    const float* Wg = W + (size_t)(bn0 + lrow) * ldw + lkq;

    for (int k = 0; k < K; k += BKK) {
        float4 av = *(const float4*)(Ag + k);
        float4 wv = *(const float4*)(Wg + k);
        As[lkq + 0][lrow] = av.x; As[lkq + 1][lrow] = av.y;
        As[lkq + 2][lrow] = av.z; As[lkq + 3][lrow] = av.w;
        Ws[lkq + 0][lrow] = wv.x; Ws[lkq + 1][lrow] = wv.y;
        Ws[lkq + 2][lrow] = wv.z; Ws[lkq + 3][lrow] = wv.w;
        __syncthreads();
#pragma unroll
        for (int kk = 0; kk < BKK; kk++) {
            float a[4], w[4];
#pragma unroll
            for (int i = 0; i < 4; i++) a[i] = As[kk][ty * 4 + i];
#pragma unroll
            for (int j = 0; j < 4; j++) w[j] = Ws[kk][tx * 4 + j];
#pragma unroll
            for (int i = 0; i < 4; i++)
#pragma unroll
                for (int j = 0; j < 4; j++) acc[i][j] += a[i] * w[j];
        }
        __syncthreads();
    }

#pragma unroll
    for (int i = 0; i < 4; i++) {
        const int r = bm0 + ty * 4 + i;
#pragma unroll
        for (int j = 0; j < 4; j++) {
            const int cc = bn0 + tx * 4 + j;
            float v = acc[i][j];
            if (bias) v += bias[cc];
            C[(size_t)r * N + cc] = v;
        }
    }
}

// ---------------- prep kernels ----------------
// reorder gate weights: Wre[i*4+g][k] = (k<HT ? W_ih[g*HI+i][HV+k] : W_hh[g*HI+i][k-HT])
__global__ void k_wre(const float* __restrict__ Wih, const float* __restrict__ Whh,
                      float* __restrict__ Wre)
{
    int idx = blockIdx.x * 256 + threadIdx.x;   // over G4*KU
    int jp = idx >> 10;
    int k  = idx & 1023;
    int i  = jp >> 2;
    int g  = jp & 3;
    int r  = g * HI + i;
    Wre[idx] = (k < HT) ? Wih[(size_t)r * (HT + HV) + HV + k]
                        : Whh[(size_t)r * HI + (k - HT)];
}

__global__ void k_biasg(const float* __restrict__ bih, const float* __restrict__ bhh,
                        float* __restrict__ biasg)
{
    int idx = blockIdx.x * 256 + threadIdx.x;
    if (idx < G4) biasg[idx] = bih[idx] + bhh[idx];
}

// ---------------- persistent scan kernel ----------------
__global__ __launch_bounds__(TPB) void k_scan(
    const float* __restrict__ h_s,
    const float* __restrict__ W_R,
    const float* __restrict__ bR,
    const float* __restrict__ Ww,
    const float* __restrict__ bw,
    float* __restrict__ out)
{
    __shared__ float sm[4608];   // 18 KB, unioned per stage

    const int bx  = blockIdx.x;
    const int tid = threadIdx.x;

    float* Sproj = g_scratch + OFF_SPROJ;
    float* Vproj = g_scratch + OFF_VPROJ;
    float* Xgv   = g_scratch + OFF_XGV;
    float* Wre   = g_scratch + OFF_WRE;
    float* Uh    = g_scratch + OFF_UH;
    float* hbuf  = g_scratch + OFF_HB;
    float* cbuf  = g_scratch + OFF_CB;
    float* xp    = g_scratch + OFF_XP;
    float* beta  = g_scratch + OFF_BETA;

    // ---- init h(-1)=0 (both buffers) and c=0 ----
    for (int idx = bx * TPB + tid; idx < (int)(SZ_HB + SZ_CB); idx += GRID * TPB) {
        if (idx < (int)SZ_HB) hbuf[idx] = 0.f;
        else                  cbuf[idx - (int)SZ_HB] = 0.f;
    }
    grid_sync();

    const float bw0 = bw[0];

    for (int t = 0; t < TT; t++) {
        const float* hp = hbuf + (size_t)(t & 1) * (BB * HI);        // h(t-1)
        float*       hn = hbuf + (size_t)((t + 1) & 1) * (BB * HI);  // h(t)

        // ================= stage A: xp[ks][b][i] partials of h_prev @ W_R^T ======
        {
            const int ks = bx >> 3;          // 0..15
            const int nt = bx & 7;           // 0..7
            const int i0 = nt * 64;
            const int k0 = ks * 32;
            float* Hs = sm;                  // [32][68]
            float* Wsh = sm + 32 * 68;       // [32][68]

            int e = tid;
#pragma unroll
            for (int r = 0; r < 8; r++, e += TPB) {
                int bb = e >> 5, kk = e & 31;
                Hs[kk * 68 + bb] = hp[(size_t)bb * HI + k0 + kk];
            }
            e = tid;
#pragma unroll
            for (int r = 0; r < 8; r++, e += TPB) {
                int jj = e >> 5, kk = e & 31;
                Wsh[kk * 68 + jj] = W_R[(size_t)(i0 + jj) * HI + k0 + kk];
            }
            __syncthreads();

            const int tx4 = (tid & 15) * 4;
            const int ty4 = (tid >> 4) * 4;
            float acc[4][4];
#pragma unroll
            for (int i = 0; i < 4; i++)
#pragma unroll
                for (int j = 0; j < 4; j++) acc[i][j] = 0.f;

#pragma unroll
            for (int kk = 0; kk < 32; kk++) {
                float4 a = *(const float4*)&Hs[kk * 68 + ty4];
                float4 w = *(const float4*)&Wsh[kk * 68 + tx4];
                float av[4] = {a.x, a.y, a.z, a.w};
                float wv[4] = {w.x, w.y, w.z, w.w};
#pragma unroll
                for (int i = 0; i < 4; i++)
#pragma unroll
                    for (int j = 0; j < 4; j++) acc[i][j] += av[i] * wv[j];
            }
#pragma unroll
            for (int i = 0; i < 4; i++) {
                float4 v = make_float4(acc[i][0], acc[i][1], acc[i][2], acc[i][3]);
                *(float4*)&xp[((size_t)ks * BB + ty4 + i) * HI + i0 + tx4] = v;
            }
        }
        grid_sync();

        // ================= stage B: reduce x + attention beta ====================
        {
            const int b  = bx >> 1;
            const int nh = bx & 1;
            float* xrow = sm;    // [512]

            for (int i = tid; i < HI; i += TPB) {
                float v = bR[i] + Vproj[((size_t)b * TT + t) * HI + i];
#pragma unroll
                for (int s = 0; s < KSPLIT; s++)
                    v += xp[((size_t)s * BB + b) * HI + i];
                xrow[i] = v;
            }
            __syncthreads();

            const int w    = tid >> 5;
            const int lane = tid & 31;
#pragma unroll
            for (int q = 0; q < 5; q++) {
                const int n = nh * 40 + w * 5 + q;
                const float* Sp = Sproj + ((size_t)b * NN + n) * HI;
                float acc = 0.f;
                for (int i = lane; i < HI; i += 32)
                    acc += fast_tanh(Sp[i] + xrow[i]) * Ww[i];
#pragma unroll
                for (int o = 16; o > 0; o >>= 1)
                    acc += __shfl_down_sync(0xffffffffu, acc, o);
                if (lane == 0) beta[n * BB + b] = acc + bw0;
            }
        }
        grid_sync();

        // ================= stage C: batch-axis softmax + H_t_s ===================
        if (bx < BB) {
            const int b = bx;
            float* al = sm;   // [80]
            if (tid < NN) {
                const int n = tid;
                float m = -1e30f;
                for (int bb = 0; bb < BB; bb++)
                    m = fmaxf(m, beta[n * BB + bb]);
                float s = 0.f;
                for (int bb = 0; bb < BB; bb++)
                    s += __expf(beta[n * BB + bb] - m);
                al[n] = __expf(beta[n * BB + b] - m) / s;
            }
            __syncthreads();
            for (int col = tid; col < HT; col += TPB) {
                float acc = 0.f;
#pragma unroll 8
                for (int n = 0; n < NN; n++)
                    acc += h_s[((size_t)b * NN + n) * HT + col] * al[n];
                Uh[(size_t)b * HT + col] = acc;
            }
        }
        grid_sync();

        // ================= stage D+E: gates GEMM + LSTM pointwise ================
        {
            const int bt = bx >> 5;          // 0..3   (16 b each)
            const int jt = bx & 31;          // 0..31  (64 reordered rows each)
            const int b0 = bt * 16;
            const int j0 = jt * 64;

            float* Us  = sm;                  // [32][18]
            float* Wsd = sm + 32 * 18;        // [32][66]
            float* gs  = sm + 32 * 18 + 32 * 66;   // [16][66]

            const int ty = tid >> 5;          // 0..7 -> b-pair ty*2
            const int tx = tid & 31;          // j-pair tx*2
            float a00 = 0.f, a01 = 0.f, a10 = 0.f, a11 = 0.f;

            for (int kc = 0; kc < KU; kc += 32) {
                int e = tid;
#pragma unroll
                for (int r = 0; r < 2; r++, e += TPB) {
                    int bb = e >> 5, kk = e & 31;
                    int kg = kc + kk;
                    float v = (kg < HT) ? Uh[(size_t)(b0 + bb) * HT + kg]
                                        : hp[(size_t)(b0 + bb) * HI + kg - HT];
                    Us[kk * 18 + bb] = v;
                }
                e = tid;
#pragma unroll
                for (int r = 0; r < 8; r++, e += TPB) {
                    int jj = e >> 5, kk = e & 31;
                    Wsd[kk * 66 + jj] = Wre[(size_t)(j0 + jj) * KU + kc + kk];
                }
                __syncthreads();
#pragma unroll
                for (int kk = 0; kk < 32; kk++) {
                    float2 a = *(const float2*)&Us[kk * 18 + ty * 2];
                    float2 w = *(const float2*)&Wsd[kk * 66 + tx * 2];
                    a00 += a.x * w.x; a01 += a.x * w.y;
                    a10 += a.y * w.x; a11 += a.y * w.y;
                }
                __syncthreads();
            }

            gs[(ty * 2 + 0) * 66 + tx * 2 + 0] = a00;
            gs[(ty * 2 + 0) * 66 + tx * 2 + 1] = a01;
            gs[(ty * 2 + 1) * 66 + tx * 2 + 0] = a10;
            gs[(ty * 2 + 1) * 66 + tx * 2 + 1] = a11;
            __syncthreads();

            // E: pointwise LSTM for (16 b x 16 i) handled by this block
            const int b_l = tid >> 4;
            const int i_l = tid & 15;
            const int b   = b0 + b_l;
            const int ig  = jt * 16 + i_l;
            const float* xg = Xgv + ((size_t)b * TT + t) * G4;

            float g0 = gs[b_l * 66 + i_l * 4 + 0] + xg[0 * HI + ig];
            float g1 = gs[b_l * 66 + i_l * 4 + 1] + xg[1 * HI + ig];
            float g2 = gs[b_l * 66 + i_l * 4 + 2] + xg[2 * HI + ig];
            float g3 = gs[b_l * 66 + i_l * 4 + 3] + xg[3 * HI + ig];

            const float ii = fast_sig(g0);
            const float ff = fast_sig(g1);
            const float gg = fast_tanh(g2);
            const float oo = fast_sig(g3);

            const size_t ci = (size_t)b * HI + ig;
            const float cn = ff * cbuf[ci] + ii * gg;
            const float hh = oo * fast_tanh(cn);
            cbuf[ci] = cn;
            hn[ci]   = hh;
            out[((size_t)b * TT + t) * HI + ig] = hh;
        }
        grid_sync();
    }
}

// ---------------- host launcher ----------------
extern "C" void kernel_launch(void* const* d_in, const int* in_sizes, int n_in,
                              void* d_out, int out_size)
{
    const float* h_v  = (const float*)d_in[0];
    const float* h_s  = (const float*)d_in[1];
    const float* W_S  = (const float*)d_in[2];
    const float* b_S  = (const float*)d_in[3];
    const float* W_V  = (const float*)d_in[4];
    const float* b_V  = (const float*)d_in[5];
    const float* W_R  = (const float*)d_in[6];
    const float* b_R  = (const float*)d_in[7];
    const float* W_w  = (const float*)d_in[8];
    const float* b_w  = (const float*)d_in[9];
    const float* W_ih = (const float*)d_in[10];
    const float* b_ih = (const float*)d_in[11];
    const float* W_hh = (const float*)d_in[12];
    const float* b_hh = (const float*)d_in[13];
    float* out = (float*)d_out;

    void* base_v = nullptr;
    cudaGetSymbolAddress(&base_v, g_scratch);
    float* base = (float*)base_v;

    float* Sproj = base + OFF_SPROJ;
    float* Vproj = base + OFF_VPROJ;
    float* Xgv   = base + OFF_XGV;
    float* Wre   = base + OFF_WRE;
    float* biasg = base + OFF_BIASG;

    // prep
    k_wre<<<(G4 * KU) / 256, 256>>>(W_ih, W_hh, Wre);
    k_biasg<<<8, 256>>>(b_ih, b_hh, biasg);

    // hoisted GEMMs
    gemm_wt<<<dim3(HI / BN, (BB * NN) / BM), 256>>>(h_s, HT, W_S, HT, b_S,
                                                    Sproj, BB * NN, HI, HT);
    gemm_wt<<<dim3(HI / BN, (BB * TT) / BM), 256>>>(h_v, HV, W_V, HV, b_V,
                                                    Vproj, BB * TT, HI, HV);
    gemm_wt<<<dim3(G4 / BN, (BB * TT) / BM), 256>>>(h_v, HV, W_ih, HT + HV, biasg,
                                                    Xgv, BB * TT, G4, HV);

    // the whole sequential scan: ONE kernel, software grid barriers
    k_scan<<<GRID, TPB>>>(h_s, W_R, b_R, W_w, b_w, out);

    (void)in_sizes; (void)n_in; (void)out_size;
}

// round 8
// speedup vs baseline: 1.0006x; 1.0006x over previous
#include <cuda_runtime.h>
#include <cstddef>

// ---------------- problem constants ----------------
#define BB 64
#define TT 512
#define NN 80
#define HT 512
#define HV 1024
#define HI 512
#define G4 2048      // 4*HI
#define KU 1024      // HT + HI

#define GRID   128   // persistent blocks (<=148 SMs -> co-resident)
#define TPB    256
#define KSPLIT 16    // stage-A split-K partials

// ---------------- scratch layout ----------------
constexpr size_t SZ_SPROJ = (size_t)BB * NN * HI;       // 2.62M
constexpr size_t SZ_VPROJ = (size_t)BB * TT * HI;       // 16.8M
constexpr size_t SZ_XGV   = (size_t)BB * TT * G4;       // 67.1M
constexpr size_t SZ_WRE   = (size_t)G4 * KU;            // 2.1M
constexpr size_t SZ_BIASG = G4;
constexpr size_t SZ_UH    = (size_t)BB * HT;            // H_t_s part
constexpr size_t SZ_HB    = (size_t)2 * BB * HI;        // h ping-pong
constexpr size_t SZ_CB    = (size_t)BB * HI;
constexpr size_t SZ_XP    = (size_t)KSPLIT * BB * HI;   // 512K
constexpr size_t SZ_BETA  = (size_t)NN * BB;

constexpr size_t OFF_SPROJ = 0;
constexpr size_t OFF_VPROJ = OFF_SPROJ + SZ_SPROJ;
constexpr size_t OFF_XGV   = OFF_VPROJ + SZ_VPROJ;
constexpr size_t OFF_WRE   = OFF_XGV   + SZ_XGV;
constexpr size_t OFF_BIASG = OFF_WRE   + SZ_WRE;
constexpr size_t OFF_UH    = OFF_BIASG + SZ_BIASG;
constexpr size_t OFF_HB    = OFF_UH    + SZ_UH;
constexpr size_t OFF_CB    = OFF_HB    + SZ_HB;
constexpr size_t OFF_XP    = OFF_CB    + SZ_CB;
constexpr size_t OFF_BETA  = OFF_XP    + SZ_XP;
constexpr size_t SZ_TOTAL  = OFF_BETA  + SZ_BETA;

__device__ float    g_scratch[SZ_TOTAL];
__device__ unsigned g_arrive = 0;
__device__ unsigned g_gen    = 0;

// ---------------- fast activations ----------------
__device__ __forceinline__ float fast_tanh(float x) {
    float e = __expf(2.f * x);
    return 1.f - 2.f / (e + 1.f);          // saturates correctly at +/-1
}
__device__ __forceinline__ float fast_sig(float x) {
    return 1.f / (1.f + __expf(-x));
}

// ---------------- software grid barrier (all GRID blocks resident) ----------------
__device__ __forceinline__ void grid_sync() {
    __syncthreads();
    if (threadIdx.x == 0) {
        __threadfence();
        volatile unsigned* vg = &g_gen;
        unsigned gen = *vg;                 // read BEFORE arriving
        if (atomicAdd(&g_arrive, 1u) == GRID - 1) {
            g_arrive = 0u;
            __threadfence();
            atomicAdd(&g_gen, 1u);
        } else {
            while (*vg == gen) { }
        }
        __threadfence();
    }
    __syncthreads();
}

// ---------------- generic tiled SGEMM: C = A[M,K] * W[N,K]^T (+bias) ----------------
#define BM 64
#define BN 64
#define BKK 16

__global__ __launch_bounds__(256) void gemm_wt(
    const float* __restrict__ A, int lda,
    const float* __restrict__ W, int ldw,
    const float* __restrict__ bias,
    float* __restrict__ C,
    int M, int N, int K)
{
    const int bn0 = blockIdx.x * BN;
    const int bm0 = blockIdx.y * BM;

    __shared__ float As[BKK][BM + 4];
    __shared__ float Ws[BKK][BN + 4];

    const int tid  = threadIdx.x;
    const int tx   = tid & 15;
    const int ty   = tid >> 4;
    const int lrow = tid >> 2;
    const int lkq  = (tid & 3) * 4;

    float acc[4][4];
#pragma unroll
    for (int i = 0; i < 4; i++)
#pragma unroll
        for (int j = 0; j < 4; j++) acc[i][j] = 0.f;

    const float* Ag = A + (size_t)(bm0 + lrow) * lda + lkq;
    const float* Wg = W + (size_t)(bn0 + lrow) * ldw + lkq;

    for (int k = 0; k < K; k += BKK) {
        float4 av = *(const float4*)(Ag + k);
        float4 wv = *(const float4*)(Wg + k);
        As[lkq + 0][lrow] = av.x; As[lkq + 1][lrow] = av.y;
        As[lkq + 2][lrow] = av.z; As[lkq + 3][lrow] = av.w;
        Ws[lkq + 0][lrow] = wv.x; Ws[lkq + 1][lrow] = wv.y;
        Ws[lkq + 2][lrow] = wv.z; Ws[lkq + 3][lrow] = wv.w;
        __syncthreads();
#pragma unroll
        for (int kk = 0; kk < BKK; kk++) {
            float a[4], w[4];
#pragma unroll
            for (int i = 0; i < 4; i++) a[i] = As[kk][ty * 4 + i];
#pragma unroll
            for (int j = 0; j < 4; j++) w[j] = Ws[kk][tx * 4 + j];
#pragma unroll
            for (int i = 0; i < 4; i++)
#pragma unroll
                for (int j = 0; j < 4; j++) acc[i][j] += a[i] * w[j];
        }
        __syncthreads();
    }

#pragma unroll
    for (int i = 0; i < 4; i++) {
        const int r = bm0 + ty * 4 + i;
#pragma unroll
        for (int j = 0; j < 4; j++) {
            const int cc = bn0 + tx * 4 + j;
            float v = acc[i][j];
            if (bias) v += bias[cc];
            C[(size_t)r * N + cc] = v;
        }
    }
}

// ---------------- prep kernels ----------------
// reorder gate weights: Wre[i*4+g][k] = (k<HT ? W_ih[g*HI+i][HV+k] : W_hh[g*HI+i][k-HT])
__global__ void k_wre(const float* __restrict__ Wih, const float* __restrict__ Whh,
                      float* __restrict__ Wre)
{
    int idx = blockIdx.x * 256 + threadIdx.x;   // over G4*KU
    int jp = idx >> 10;
    int k  = idx & 1023;
    int i  = jp >> 2;
    int g  = jp & 3;
    int r  = g * HI + i;
    Wre[idx] = (k < HT) ? Wih[(size_t)r * (HT + HV) + HV + k]
                        : Whh[(size_t)r * HI + (k - HT)];
}

__global__ void k_biasg(const float* __restrict__ bih, const float* __restrict__ bhh,
                        float* __restrict__ biasg)
{
    int idx = blockIdx.x * 256 + threadIdx.x;
    if (idx < G4) biasg[idx] = bih[idx] + bhh[idx];
}

// ---------------- persistent scan kernel ----------------
__global__ __launch_bounds__(TPB) void k_scan(
    const float* __restrict__ h_s,
    const float* __restrict__ W_R,
    const float* __restrict__ bR,
    const float* __restrict__ Ww,
    const float* __restrict__ bw,
    float* __restrict__ out)
{
    __shared__ float sm[4608];   // 18 KB, unioned per stage

    const int bx  = blockIdx.x;
    const int tid = threadIdx.x;

    float* Sproj = g_scratch + OFF_SPROJ;
    float* Vproj = g_scratch + OFF_VPROJ;
    float* Xgv   = g_scratch + OFF_XGV;
    float* Wre   = g_scratch + OFF_WRE;
    float* Uh    = g_scratch + OFF_UH;
    float* hbuf  = g_scratch + OFF_HB;
    float* cbuf  = g_scratch + OFF_CB;
    float* xp    = g_scratch + OFF_XP;
    float* beta  = g_scratch + OFF_BETA;

    // ---- init h(-1)=0 (both buffers) and c=0 ----
    for (int idx = bx * TPB + tid; idx < (int)(SZ_HB + SZ_CB); idx += GRID * TPB) {
        if (idx < (int)SZ_HB) hbuf[idx] = 0.f;
        else                  cbuf[idx - (int)SZ_HB] = 0.f;
    }
    grid_sync();

    const float bw0 = bw[0];

    for (int t = 0; t < TT; t++) {
        const float* hp = hbuf + (size_t)(t & 1) * (BB * HI);        // h(t-1)
        float*       hn = hbuf + (size_t)((t + 1) & 1) * (BB * HI);  // h(t)

        // ================= stage A: xp[ks][b][i] partials of h_prev @ W_R^T ======
        {
            const int ks = bx >> 3;          // 0..15
            const int nt = bx & 7;           // 0..7
            const int i0 = nt * 64;
            const int k0 = ks * 32;
            float* Hs = sm;                  // [32][68]
            float* Wsh = sm + 32 * 68;       // [32][68]

            int e = tid;
#pragma unroll
            for (int r = 0; r < 8; r++, e += TPB) {
                int bb = e >> 5, kk = e & 31;
                Hs[kk * 68 + bb] = hp[(size_t)bb * HI + k0 + kk];
            }
            e = tid;
#pragma unroll
            for (int r = 0; r < 8; r++, e += TPB) {
                int jj = e >> 5, kk = e & 31;
                Wsh[kk * 68 + jj] = W_R[(size_t)(i0 + jj) * HI + k0 + kk];
            }
            __syncthreads();

            const int tx4 = (tid & 15) * 4;
            const int ty4 = (tid >> 4) * 4;
            float acc[4][4];
#pragma unroll
            for (int i = 0; i < 4; i++)
#pragma unroll
                for (int j = 0; j < 4; j++) acc[i][j] = 0.f;

#pragma unroll
            for (int kk = 0; kk < 32; kk++) {
                float4 a = *(const float4*)&Hs[kk * 68 + ty4];
                float4 w = *(const float4*)&Wsh[kk * 68 + tx4];
                float av[4] = {a.x, a.y, a.z, a.w};
                float wv[4] = {w.x, w.y, w.z, w.w};
#pragma unroll
                for (int i = 0; i < 4; i++)
#pragma unroll
                    for (int j = 0; j < 4; j++) acc[i][j] += av[i] * wv[j];
            }
#pragma unroll
            for (int i = 0; i < 4; i++) {
                float4 v = make_float4(acc[i][0], acc[i][1], acc[i][2], acc[i][3]);
                *(float4*)&xp[((size_t)ks * BB + ty4 + i) * HI + i0 + tx4] = v;
            }
        }
        grid_sync();

        // ================= stage B: reduce x + attention beta ====================
        {
            const int b  = bx >> 1;
            const int nh = bx & 1;
            float* xrow = sm;    // [512]

            for (int i = tid; i < HI; i += TPB) {
                float v = bR[i] + Vproj[((size_t)b * TT + t) * HI + i];
#pragma unroll
                for (int s = 0; s < KSPLIT; s++)
                    v += xp[((size_t)s * BB + b) * HI + i];
                xrow[i] = v;
            }
            __syncthreads();

            const int w    = tid >> 5;
            const int lane = tid & 31;
#pragma unroll
            for (int q = 0; q < 5; q++) {
                const int n = nh * 40 + w * 5 + q;
                const float* Sp = Sproj + ((size_t)b * NN + n) * HI;
                float acc = 0.f;
                for (int i = lane; i < HI; i += 32)
                    acc += fast_tanh(Sp[i] + xrow[i]) * Ww[i];
#pragma unroll
                for (int o = 16; o > 0; o >>= 1)
                    acc += __shfl_down_sync(0xffffffffu, acc, o);
                if (lane == 0) beta[n * BB + b] = acc + bw0;
            }
        }
        grid_sync();

        // ================= stage C: batch-axis softmax + H_t_s ===================
        if (bx < BB) {
            const int b = bx;
            float* al = sm;   // [80]
            if (tid < NN) {
                const int n = tid;
                float m = -1e30f;
                for (int bb = 0; bb < BB; bb++)
                    m = fmaxf(m, beta[n * BB + bb]);
                float s = 0.f;
                for (int bb = 0; bb < BB; bb++)
                    s += __expf(beta[n * BB + bb] - m);
                al[n] = __expf(beta[n * BB + b] - m) / s;
            }
            __syncthreads();
            for (int col = tid; col < HT; col += TPB) {
                float acc = 0.f;
#pragma unroll 8
                for (int n = 0; n < NN; n++)
                    acc += h_s[((size_t)b * NN + n) * HT + col] * al[n];
                Uh[(size_t)b * HT + col] = acc;
            }
        }
        grid_sync();

        // ================= stage D+E: gates GEMM + LSTM pointwise ================
        {
            const int bt = bx >> 5;          // 0..3   (16 b each)
            const int jt = bx & 31;          // 0..31  (64 reordered rows each)
            const int b0 = bt * 16;
            const int j0 = jt * 64;

            float* Us  = sm;                  // [32][18]
            float* Wsd = sm + 32 * 18;        // [32][66]
            float* gs  = sm + 32 * 18 + 32 * 66;   // [16][66]

            const int ty = tid >> 5;          // 0..7 -> b-pair ty*2
            const int tx = tid & 31;          // j-pair tx*2
            float a00 = 0.f, a01 = 0.f, a10 = 0.f, a11 = 0.f;

            for (int kc = 0; kc < KU; kc += 32) {
                int e = tid;
#pragma unroll
                for (int r = 0; r < 2; r++, e += TPB) {
                    int bb = e >> 5, kk = e & 31;
                    int kg = kc + kk;
                    float v = (kg < HT) ? Uh[(size_t)(b0 + bb) * HT + kg]
                                        : hp[(size_t)(b0 + bb) * HI + kg - HT];
                    Us[kk * 18 + bb] = v;
                }
                e = tid;
#pragma unroll
                for (int r = 0; r < 8; r++, e += TPB) {
                    int jj = e >> 5, kk = e & 31;
                    Wsd[kk * 66 + jj] = Wre[(size_t)(j0 + jj) * KU + kc + kk];
                }
                __syncthreads();
#pragma unroll
                for (int kk = 0; kk < 32; kk++) {
                    float2 a = *(const float2*)&Us[kk * 18 + ty * 2];
                    float2 w = *(const float2*)&Wsd[kk * 66 + tx * 2];
                    a00 += a.x * w.x; a01 += a.x * w.y;
                    a10 += a.y * w.x; a11 += a.y * w.y;
                }
                __syncthreads();
            }

            gs[(ty * 2 + 0) * 66 + tx * 2 + 0] = a00;
            gs[(ty * 2 + 0) * 66 + tx * 2 + 1] = a01;
            gs[(ty * 2 + 1) * 66 + tx * 2 + 0] = a10;
            gs[(ty * 2 + 1) * 66 + tx * 2 + 1] = a11;
            __syncthreads();

            // E: pointwise LSTM for (16 b x 16 i) handled by this block
            const int b_l = tid >> 4;
            const int i_l = tid & 15;
            const int b   = b0 + b_l;
            const int ig  = jt * 16 + i_l;
            const float* xg = Xgv + ((size_t)b * TT + t) * G4;

            float g0 = gs[b_l * 66 + i_l * 4 + 0] + xg[0 * HI + ig];
            float g1 = gs[b_l * 66 + i_l * 4 + 1] + xg[1 * HI + ig];
            float g2 = gs[b_l * 66 + i_l * 4 + 2] + xg[2 * HI + ig];
            float g3 = gs[b_l * 66 + i_l * 4 + 3] + xg[3 * HI + ig];

            const float ii = fast_sig(g0);
            const float ff = fast_sig(g1);
            const float gg = fast_tanh(g2);
            const float oo = fast_sig(g3);

            const size_t ci = (size_t)b * HI + ig;
            const float cn = ff * cbuf[ci] + ii * gg;
            const float hh = oo * fast_tanh(cn);
            cbuf[ci] = cn;
            hn[ci]   = hh;
            out[((size_t)b * TT + t) * HI + ig] = hh;
        }
        grid_sync();
    }
}

// ---------------- host launcher ----------------
extern "C" void kernel_launch(void* const* d_in, const int* in_sizes, int n_in,
                              void* d_out, int out_size)
{
    const float* h_v  = (const float*)d_in[0];
    const float* h_s  = (const float*)d_in[1];
    const float* W_S  = (const float*)d_in[2];
    const float* b_S  = (const float*)d_in[3];
    const float* W_V  = (const float*)d_in[4];
    const float* b_V  = (const float*)d_in[5];
    const float* W_R  = (const float*)d_in[6];
    const float* b_R  = (const float*)d_in[7];
    const float* W_w  = (const float*)d_in[8];
    const float* b_w  = (const float*)d_in[9];
    const float* W_ih = (const float*)d_in[10];
    const float* b_ih = (const float*)d_in[11];
    const float* W_hh = (const float*)d_in[12];
    const float* b_hh = (const float*)d_in[13];
    float* out = (float*)d_out;

    void* base_v = nullptr;
    cudaGetSymbolAddress(&base_v, g_scratch);
    float* base = (float*)base_v;

    float* Sproj = base + OFF_SPROJ;
    float* Vproj = base + OFF_VPROJ;
    float* Xgv   = base + OFF_XGV;
    float* Wre   = base + OFF_WRE;
    float* biasg = base + OFF_BIASG;

    // prep
    k_wre<<<(G4 * KU) / 256, 256>>>(W_ih, W_hh, Wre);
    k_biasg<<<8, 256>>>(b_ih, b_hh, biasg);

    // hoisted GEMMs
    gemm_wt<<<dim3(HI / BN, (BB * NN) / BM), 256>>>(h_s, HT, W_S, HT, b_S,
                                                    Sproj, BB * NN, HI, HT);
    gemm_wt<<<dim3(HI / BN, (BB * TT) / BM), 256>>>(h_v, HV, W_V, HV, b_V,
                                                    Vproj, BB * TT, HI, HV);
    gemm_wt<<<dim3(G4 / BN, (BB * TT) / BM), 256>>>(h_v, HV, W_ih, HT + HV, biasg,
                                                    Xgv, BB * TT, G4, HV);

    // the whole sequential scan: ONE kernel, software grid barriers
    k_scan<<<GRID, TPB>>>(h_s, W_R, b_R, W_w, b_w, out);

    (void)in_sizes; (void)n_in; (void)out_size;
}

// round 10
// speedup vs baseline: 2.1791x; 2.1777x over previous
#include <cuda_runtime.h>
#include <cuda_bf16.h>
#include <cstddef>

// ---------------- problem constants ----------------
#define BB 64
#define TT 512
#define NN 80
#define HT 512
#define HV 1024
#define HI 512
#define G4 2048      // 4*HI
#define NCAT 2560    // 512 (r_proj cols) + 2048 (hh gate cols)

#define GRID   128
#define TPB    256
#define NSLAB  16    // K=512 in 16 slabs of 32
#define IPB    5     // items per block: 40 ntiles * 16 slabs / 128 blocks

// ---------------- scratch layout (floats) ----------------
constexpr size_t SZ_SPROJ = (size_t)BB * NN * HI;        // 2.62M
constexpr size_t SZ_VPROJ = (size_t)BB * TT * HI;        // 16.8M
constexpr size_t SZ_XGV   = (size_t)BB * TT * G4;        // 67.1M (reordered cols)
constexpr size_t SZ_PF    = (size_t)BB * NN * G4;        // 10.5M fp32 P
constexpr size_t SZ_PB    = (size_t)BB * NN * G4 / 2;    // bf16 P in float units
constexpr size_t SZ_WREV  = (size_t)G4 * HV;             // reordered visual gate W
constexpr size_t SZ_WRES  = (size_t)G4 * HT;             // reordered textual gate W
constexpr size_t SZ_WCAT2 = (size_t)NCAT * HI;           // [W_R ; W_hh_re]
constexpr size_t SZ_BIASG = G4;
constexpr size_t SZ_HB    = (size_t)2 * BB * HI;
constexpr size_t SZ_CB    = (size_t)BB * HI;
constexpr size_t SZ_PBUF  = (size_t)NSLAB * BB * NCAT;   // 2.62M
constexpr size_t SZ_EB    = (size_t)NN * BB;

constexpr size_t OFF_SPROJ = 0;
constexpr size_t OFF_VPROJ = OFF_SPROJ + SZ_SPROJ;
constexpr size_t OFF_XGV   = OFF_VPROJ + SZ_VPROJ;
constexpr size_t OFF_PF    = OFF_XGV   + SZ_XGV;
constexpr size_t OFF_PB    = OFF_PF    + SZ_PF;
constexpr size_t OFF_WREV  = OFF_PB    + SZ_PB;
constexpr size_t OFF_WRES  = OFF_WREV  + SZ_WREV;
constexpr size_t OFF_WCAT2 = OFF_WRES  + SZ_WRES;
constexpr size_t OFF_BIASG = OFF_WCAT2 + SZ_WCAT2;
constexpr size_t OFF_HB    = OFF_BIASG + SZ_BIASG;
constexpr size_t OFF_CB    = OFF_HB    + SZ_HB;
constexpr size_t OFF_PBUF  = OFF_CB    + SZ_CB;
constexpr size_t OFF_EB    = OFF_PBUF  + SZ_PBUF;
constexpr size_t SZ_TOTAL  = OFF_EB    + SZ_EB;

__device__ float    g_scratch[SZ_TOTAL];
__device__ unsigned g_arrive = 0;
__device__ unsigned g_gen    = 0;

// ---------------- fast activations (LSTM pointwise only; small counts) ----------
__device__ __forceinline__ float fast_tanh(float x) {
    float e = __expf(2.f * x);
    return 1.f - 2.f / (e + 1.f);
}
__device__ __forceinline__ float fast_sig(float x) {
    return 1.f / (1.f + __expf(-x));
}

// ---------------- software grid barrier ----------------
__device__ __forceinline__ void grid_sync() {
    __syncthreads();
    if (threadIdx.x == 0) {
        __threadfence();
        volatile unsigned* vg = &g_gen;
        unsigned gen = *vg;
        if (atomicAdd(&g_arrive, 1u) == GRID - 1) {
            g_arrive = 0u;
            __threadfence();
            atomicAdd(&g_gen, 1u);
        } else {
            while (*vg == gen) { }
        }
        __threadfence();
    }
    __syncthreads();
}

// ---------------- generic tiled SGEMM: C = A[M,K] * W[N,K]^T (+bias) ----------
#define BM 64
#define BN 64
#define BKK 16

__global__ __launch_bounds__(256) void gemm_wt(
    const float* __restrict__ A, int lda,
    const float* __restrict__ W, int ldw,
    const float* __restrict__ bias,
    float* __restrict__ C,
    int M, int N, int K)
{
    const int bn0 = blockIdx.x * BN;
    const int bm0 = blockIdx.y * BM;

    __shared__ float As[BKK][BM + 4];
    __shared__ float Ws[BKK][BN + 4];

    const int tid  = threadIdx.x;
    const int tx   = tid & 15;
    const int ty   = tid >> 4;
    const int lrow = tid >> 2;
    const int lkq  = (tid & 3) * 4;

    float acc[4][4];
#pragma unroll
    for (int i = 0; i < 4; i++)
#pragma unroll
        for (int j = 0; j < 4; j++) acc[i][j] = 0.f;

    const float* Ag = A + (size_t)(bm0 + lrow) * lda + lkq;
    const float* Wg = W + (size_t)(bn0 + lrow) * ldw + lkq;

    for (int k = 0; k < K; k += BKK) {
        float4 av = *(const float4*)(Ag + k);
        float4 wv = *(const float4*)(Wg + k);
        As[lkq + 0][lrow] = av.x; As[lkq + 1][lrow] = av.y;
        As[lkq + 2][lrow] = av.z; As[lkq + 3][lrow] = av.w;
        Ws[lkq + 0][lrow] = wv.x; Ws[lkq + 1][lrow] = wv.y;
        Ws[lkq + 2][lrow] = wv.z; Ws[lkq + 3][lrow] = wv.w;
        __syncthreads();
#pragma unroll
        for (int kk = 0; kk < BKK; kk++) {
            float a[4], w[4];
#pragma unroll
            for (int i = 0; i < 4; i++) a[i] = As[kk][ty * 4 + i];
#pragma unroll
            for (int j = 0; j < 4; j++) w[j] = Ws[kk][tx * 4 + j];
#pragma unroll
            for (int i = 0; i < 4; i++)
#pragma unroll
                for (int j = 0; j < 4; j++) acc[i][j] += a[i] * w[j];
        }
        __syncthreads();
    }

#pragma unroll
    for (int i = 0; i < 4; i++) {
        const int r = bm0 + ty * 4 + i;
#pragma unroll
        for (int j = 0; j < 4; j++) {
            const int cc = bn0 + tx * 4 + j;
            float v = acc[i][j];
            if (bias) v += bias[cc];
            C[(size_t)r * N + cc] = v;
        }
    }
}

// ---------------- prep kernels ----------------
// reordered col index: j = i*4 + g  <->  original gate row r = g*HI + i
__global__ void k_reorder_v(const float* __restrict__ Wih, float* __restrict__ Wrev)
{
    int idx = blockIdx.x * 256 + threadIdx.x;      // G4*HV
    int j = idx >> 10, k = idx & 1023;
    int i = j >> 2, g = j & 3;
    Wrev[idx] = Wih[(size_t)(g * HI + i) * (HT + HV) + k];   // visual cols [0,HV)
}
__global__ void k_reorder_s(const float* __restrict__ Wih, float* __restrict__ Wres)
{
    int idx = blockIdx.x * 256 + threadIdx.x;      // G4*HT
    int j = idx >> 9, k = idx & 511;
    int i = j >> 2, g = j & 3;
    Wres[idx] = Wih[(size_t)(g * HI + i) * (HT + HV) + HV + k];
}
__global__ void k_wcat2(const float* __restrict__ WR, const float* __restrict__ Whh,
                        float* __restrict__ Wc)
{
    int idx = blockIdx.x * 256 + threadIdx.x;      // NCAT*HI
    int r = idx >> 9, k = idx & 511;
    if (r < HI) Wc[idx] = WR[(size_t)r * HI + k];
    else {
        int j = r - HI, i = j >> 2, g = j & 3;
        Wc[idx] = Whh[(size_t)(g * HI + i) * HI + k];
    }
}
__global__ void k_biasg(const float* __restrict__ bih, const float* __restrict__ bhh,
                        float* __restrict__ bg)
{
    int j = blockIdx.x * 256 + threadIdx.x;
    if (j < G4) {
        int i = j >> 2, g = j & 3;
        bg[j] = bih[g * HI + i] + bhh[g * HI + i];
    }
}
__global__ void k_tobf16(const float* __restrict__ src, __nv_bfloat16* __restrict__ dst,
                         size_t n)
{
    size_t idx = (size_t)blockIdx.x * 256 + threadIdx.x;
    if (idx < n) dst[idx] = __float2bfloat16(src[idx]);
}

// ---------------- persistent scan kernel ----------------
__global__ __launch_bounds__(TPB) void k_scan(
    const float* __restrict__ bR,
    const float* __restrict__ Ww,
    const float* __restrict__ bw,
    float* __restrict__ out)
{
    __shared__ float  sm[4608];       // stage-unioned
    __shared__ float2 ttab[520];      // tanh LUT over [-4,4], step 1/64
    __shared__ float  ww_s[512];
    __shared__ float  bR_s[512];

    const int bx  = blockIdx.x;
    const int tid = threadIdx.x;

    float* Sproj = g_scratch + OFF_SPROJ;
    float* Vproj = g_scratch + OFF_VPROJ;
    float* Xgv   = g_scratch + OFF_XGV;
    float* Wcat2 = g_scratch + OFF_WCAT2;
    float* hbuf  = g_scratch + OFF_HB;
    float* cbuf  = g_scratch + OFF_CB;
    float* pbuf  = g_scratch + OFF_PBUF;
    float* eb    = g_scratch + OFF_EB;
    const __nv_bfloat16* Pb = (const __nv_bfloat16*)(g_scratch + OFF_PB);

    // one-time per-block setup
    for (int i = tid; i < 520; i += TPB) {
        float x0 = -4.f + (float)i * (1.f / 64.f);
        float v0 = tanhf(x0);
        float v1 = tanhf(x0 + (1.f / 64.f));
        ttab[i] = make_float2(v0, v1 - v0);
    }
    for (int i = tid; i < 512; i += TPB) { ww_s[i] = Ww[i]; bR_s[i] = bR[i]; }
    for (int idx = bx * TPB + tid; idx < (int)(SZ_HB + SZ_CB); idx += GRID * TPB) {
        if (idx < (int)SZ_HB) hbuf[idx] = 0.f;
        else                  cbuf[idx - (int)SZ_HB] = 0.f;
    }
    const float bw0 = bw[0];
    grid_sync();

    for (int t = 0; t < TT; t++) {
        const float* hp = hbuf + (size_t)(t & 1) * (BB * HI);
        float*       hn = hbuf + (size_t)((t + 1) & 1) * (BB * HI);

        // ========= stage A: combined GEMM  pbuf[sl][b][col] = hp @ Wcat2^T slabs ====
        {
            float* Hs  = sm;             // [32][68] k x b
            float* Wsh = sm + 32 * 68;   // [32][68] k x col
            const int tx4 = (tid & 15) * 4;
            const int ty4 = (tid >> 4) * 4;
#pragma unroll
            for (int q = 0; q < IPB; q++) {
                const int item = bx * IPB + q;          // 0..639
                const int nt   = item >> 4;             // 0..39
                const int sl   = item & 15;             // 0..15
                const int col0 = nt * 64;
                const int k0   = sl * 32;
                __syncthreads();
                int e = tid;
#pragma unroll
                for (int r = 0; r < 8; r++, e += TPB) {
                    int a2 = e >> 5, kk = e & 31;
                    Hs[kk * 68 + a2] = hp[(size_t)a2 * HI + k0 + kk];
                }
                e = tid;
#pragma unroll
                for (int r = 0; r < 8; r++, e += TPB) {
                    int jj = e >> 5, kk = e & 31;
                    Wsh[kk * 68 + jj] = Wcat2[(size_t)(col0 + jj) * HI + k0 + kk];
                }
                __syncthreads();
                float acc[4][4];
#pragma unroll
                for (int i = 0; i < 4; i++)
#pragma unroll
                    for (int j = 0; j < 4; j++) acc[i][j] = 0.f;
#pragma unroll
                for (int kk = 0; kk < 32; kk++) {
                    float4 a = *(const float4*)&Hs[kk * 68 + ty4];
                    float4 w = *(const float4*)&Wsh[kk * 68 + tx4];
                    float av[4] = {a.x, a.y, a.z, a.w};
                    float wv[4] = {w.x, w.y, w.z, w.w};
#pragma unroll
                    for (int i = 0; i < 4; i++)
#pragma unroll
                        for (int j = 0; j < 4; j++) acc[i][j] += av[i] * wv[j];
                }
#pragma unroll
                for (int i = 0; i < 4; i++) {
                    float4 v = make_float4(acc[i][0], acc[i][1], acc[i][2], acc[i][3]);
                    *(float4*)&pbuf[((size_t)sl * BB + ty4 + i) * NCAT + col0 + tx4] = v;
                }
            }
        }
        grid_sync();

        // ========= stage B: x-reduce + LUT-tanh attention -> eb = exp(beta) =========
        {
            const int b  = bx >> 1;
            const int nh = bx & 1;
            float* xrow = sm;

            for (int i = tid; i < HI; i += TPB) {
                float v = bR_s[i] + Vproj[((size_t)b * TT + t) * HI + i];
#pragma unroll
                for (int sl = 0; sl < NSLAB; sl++)
                    v += pbuf[((size_t)sl * BB + b) * NCAT + i];
                xrow[i] = v;
            }
            __syncthreads();

            const int w    = tid >> 5;
            const int lane = tid & 31;
#pragma unroll
            for (int q = 0; q < 5; q++) {
                const int n = nh * 40 + w * 5 + q;
                const float* Sp = Sproj + ((size_t)b * NN + n) * HI;
                float acc = 0.f;
#pragma unroll 4
                for (int i = lane; i < HI; i += 32) {
                    float x = Sp[i] + xrow[i];
                    float p = fminf(fmaxf(x, -4.f), 4.f) * 64.f + 256.f;
                    int   ix = (int)p;
                    float fr = p - (float)ix;
                    float2 en = ttab[ix];
                    acc += fmaf(en.y, fr, en.x) * ww_s[i];
                }
#pragma unroll
                for (int o = 16; o > 0; o >>= 1)
                    acc += __shfl_down_sync(0xffffffffu, acc, o);
                if (lane == 0) eb[n * BB + b] = __expf(acc + bw0);
            }
        }
        grid_sync();

        // ========= stage C: softmax + gate assembly (P-weighted) + LSTM ============
        {
            const int b = bx >> 1;
            const int h = bx & 1;
            float* al = sm;   // alpha[n] for this b

            if (tid < NN) {
                const float* er = eb + tid * BB;
                float s = 0.f;
#pragma unroll
                for (int bb = 0; bb < BB; bb += 4) {
                    float4 v = *(const float4*)&er[bb];
                    s += v.x + v.y + v.z + v.w;
                }
                al[tid] = er[b] / s;
            }
            __syncthreads();

            const int j  = h * 1024 + tid * 4;   // 4 consecutive reordered cols = 4 gates of one i
            const int ii = h * 256 + tid;

            float4 acc = *(const float4*)&Xgv[((size_t)b * TT + t) * G4 + j];
#pragma unroll
            for (int sl = 0; sl < NSLAB; sl++) {
                float4 p = *(const float4*)&pbuf[((size_t)sl * BB + b) * NCAT + HI + j];
                acc.x += p.x; acc.y += p.y; acc.z += p.z; acc.w += p.w;
            }

            const __nv_bfloat16* Pp = Pb + (size_t)b * NN * G4 + j;
#pragma unroll 16
            for (int n = 0; n < NN; n++) {
                float a = al[n];
                uint2 raw = *(const uint2*)(Pp + (size_t)n * G4);
                float2 lo = __bfloat1622float2(*(const __nv_bfloat162*)&raw.x);
                float2 hi = __bfloat1622float2(*(const __nv_bfloat162*)&raw.y);
                acc.x = fmaf(a, lo.x, acc.x);
                acc.y = fmaf(a, lo.y, acc.y);
                acc.z = fmaf(a, hi.x, acc.z);
                acc.w = fmaf(a, hi.y, acc.w);
            }

            const float ig = fast_sig(acc.x);
            const float fg = fast_sig(acc.y);
            const float gg = fast_tanh(acc.z);
            const float og = fast_sig(acc.w);

            const size_t ci = (size_t)b * HI + ii;
            const float cn = fg * cbuf[ci] + ig * gg;
            const float hh = og * fast_tanh(cn);
            cbuf[ci] = cn;
            hn[ci]   = hh;
            out[((size_t)b * TT + t) * HI + ii] = hh;
        }
        grid_sync();
    }
}

// ---------------- host launcher ----------------
extern "C" void kernel_launch(void* const* d_in, const int* in_sizes, int n_in,
                              void* d_out, int out_size)
{
    const float* h_v  = (const float*)d_in[0];
    const float* h_s  = (const float*)d_in[1];
    const float* W_S  = (const float*)d_in[2];
    const float* b_S  = (const float*)d_in[3];
    const float* W_V  = (const float*)d_in[4];
    const float* b_V  = (const float*)d_in[5];
    const float* W_R  = (const float*)d_in[6];
    const float* b_R  = (const float*)d_in[7];
    const float* W_w  = (const float*)d_in[8];
    const float* b_w  = (const float*)d_in[9];
    const float* W_ih = (const float*)d_in[10];
    const float* b_ih = (const float*)d_in[11];
    const float* W_hh = (const float*)d_in[12];
    const float* b_hh = (const float*)d_in[13];
    float* out = (float*)d_out;

    void* base_v = nullptr;
    cudaGetSymbolAddress(&base_v, g_scratch);
    float* base = (float*)base_v;

    float* Sproj = base + OFF_SPROJ;
    float* Vproj = base + OFF_VPROJ;
    float* Xgv   = base + OFF_XGV;
    float* Pf    = base + OFF_PF;
    __nv_bfloat16* Pbf = (__nv_bfloat16*)(base + OFF_PB);
    float* Wrev  = base + OFF_WREV;
    float* Wres  = base + OFF_WRES;
    float* Wcat2 = base + OFF_WCAT2;
    float* biasg = base + OFF_BIASG;

    // prep (weight reorders)
    k_reorder_v<<<(G4 * HV) / 256, 256>>>(W_ih, Wrev);
    k_reorder_s<<<(G4 * HT) / 256, 256>>>(W_ih, Wres);
    k_wcat2<<<(NCAT * HI) / 256, 256>>>(W_R, W_hh, Wcat2);
    k_biasg<<<8, 256>>>(b_ih, b_hh, biasg);

    // hoisted GEMMs
    gemm_wt<<<dim3(HI / BN, (BB * NN) / BM), 256>>>(h_s, HT, W_S, HT, b_S,
                                                    Sproj, BB * NN, HI, HT);
    gemm_wt<<<dim3(HI / BN, (BB * TT) / BM), 256>>>(h_v, HV, W_V, HV, b_V,
                                                    Vproj, BB * TT, HI, HV);
    gemm_wt<<<dim3(G4 / BN, (BB * TT) / BM), 256>>>(h_v, HV, Wrev, HV, biasg,
                                                    Xgv, BB * TT, G4, HV);
    gemm_wt<<<dim3(G4 / BN, (BB * NN) / BM), 256>>>(h_s, HT, Wres, HT, nullptr,
                                                    Pf, BB * NN, G4, HT);
    k_tobf16<<<(int)((SZ_PF + 255) / 256), 256>>>(Pf, Pbf, SZ_PF);

    // the whole sequential scan: ONE kernel, 3 grid barriers per step
    k_scan<<<GRID, TPB>>>(b_R, W_w, b_w, out);

    (void)in_sizes; (void)n_in; (void)out_size;
}

// round 11
// speedup vs baseline: 2.6975x; 1.2379x over previous
#include <cuda_runtime.h>
#include <cuda_bf16.h>
#include <cstdint>
#include <cstddef>

// ---------------- problem constants ----------------
#define BB 64
#define TT 512
#define NN 80
#define HT 512
#define HV 1024
#define HI 512
#define G4 2048      // 4*HI
#define NCAT 2560    // 512 (r_proj cols) + 2048 (hh gate cols)

#define GRID   128
#define TPB    256
#define NSLAB  16    // K=512 in 16 slabs of 32
#define IPB    5     // items per block: 40 ntiles * 16 slabs / 128 blocks

// ---------------- scratch layout (floats) ----------------
constexpr size_t SZ_SPROJ = (size_t)BB * NN * HI;
constexpr size_t SZ_VPROJ = (size_t)BB * TT * HI;
constexpr size_t SZ_XGV   = (size_t)BB * TT * G4;
constexpr size_t SZ_PF    = (size_t)BB * NN * G4;
constexpr size_t SZ_PB    = (size_t)BB * NN * G4 / 2;
constexpr size_t SZ_WREV  = (size_t)G4 * HV;
constexpr size_t SZ_WRES  = (size_t)G4 * HT;
constexpr size_t SZ_WCAT2 = (size_t)NCAT * HI;
constexpr size_t SZ_BIASG = G4;
constexpr size_t SZ_HB    = (size_t)2 * BB * HI;
constexpr size_t SZ_CB    = (size_t)BB * HI;
constexpr size_t SZ_PBUF  = (size_t)NSLAB * BB * NCAT;
constexpr size_t SZ_EB    = (size_t)NN * BB;

constexpr size_t OFF_SPROJ = 0;
constexpr size_t OFF_VPROJ = OFF_SPROJ + SZ_SPROJ;
constexpr size_t OFF_XGV   = OFF_VPROJ + SZ_VPROJ;
constexpr size_t OFF_PF    = OFF_XGV   + SZ_XGV;
constexpr size_t OFF_PB    = OFF_PF    + SZ_PF;
constexpr size_t OFF_WREV  = OFF_PB    + SZ_PB;
constexpr size_t OFF_WRES  = OFF_WREV  + SZ_WREV;
constexpr size_t OFF_WCAT2 = OFF_WRES  + SZ_WRES;
constexpr size_t OFF_BIASG = OFF_WCAT2 + SZ_WCAT2;
constexpr size_t OFF_HB    = OFF_BIASG + SZ_BIASG;
constexpr size_t OFF_CB    = OFF_HB    + SZ_HB;
constexpr size_t OFF_PBUF  = OFF_CB    + SZ_CB;
constexpr size_t OFF_EB    = OFF_PBUF  + SZ_PBUF;
constexpr size_t SZ_TOTAL  = OFF_EB    + SZ_EB;

__device__ float    g_scratch[SZ_TOTAL];
__device__ unsigned g_arrive = 0;
__device__ unsigned g_gen    = 0;

// ---------------- fast activations ----------------
__device__ __forceinline__ float fast_tanh(float x) {
    float e = __expf(2.f * x);
    return 1.f - 2.f / (e + 1.f);
}
__device__ __forceinline__ float fast_sig(float x) {
    return 1.f / (1.f + __expf(-x));
}

// ---------------- software grid barrier ----------------
__device__ __forceinline__ void grid_sync() {
    __syncthreads();
    if (threadIdx.x == 0) {
        __threadfence();
        volatile unsigned* vg = &g_gen;
        unsigned gen = *vg;
        if (atomicAdd(&g_arrive, 1u) == GRID - 1) {
            g_arrive = 0u;
            __threadfence();
            atomicAdd(&g_gen, 1u);
        } else {
            while (*vg == gen) { }
        }
        __threadfence();
    }
    __syncthreads();
}

// ---------------- tf32 tensor-core GEMM: C = A[M,K] * W[N,K]^T (+bias) ------
// block 256 thr, tile 128x128, k-chunk 16, double-buffered, mma.sync tf32
#define TM 128
#define TN 128
#define TKC 16
#define SSTR 20     // smem row stride (floats) -> conflict-free frag loads

__device__ __forceinline__ uint32_t f2tf32(float x) {
    uint32_t r;
    asm("cvt.rna.tf32.f32 %0, %1;" : "=r"(r) : "f"(x));
    return r;
}

#define MMA_TF32(d, a, b)                                                     \
    asm volatile("mma.sync.aligned.m16n8k8.row.col.f32.tf32.tf32.f32 "        \
                 "{%0,%1,%2,%3}, {%4,%5,%6,%7}, {%8,%9}, {%0,%1,%2,%3};"      \
                 : "+f"((d)[0]), "+f"((d)[1]), "+f"((d)[2]), "+f"((d)[3])     \
                 : "r"((a)[0]), "r"((a)[1]), "r"((a)[2]), "r"((a)[3]),        \
                   "r"((b)[0]), "r"((b)[1]))

__global__ __launch_bounds__(256, 2) void gemm_tf32(
    const float* __restrict__ A, int lda,
    const float* __restrict__ W, int ldw,
    const float* __restrict__ bias,
    float* __restrict__ C,
    int M, int N, int K)
{
    __shared__ uint32_t As[2][TM * SSTR];
    __shared__ uint32_t Ws[2][TN * SSTR];

    const int tid  = threadIdx.x;
    const int lane = tid & 31;
    const int wid  = tid >> 5;
    const int wm   = (wid & 1) * 64;     // warp m-offset
    const int wn   = (wid >> 1) * 32;    // warp n-offset
    const int g    = lane >> 2;          // group 0..7
    const int tg   = lane & 3;           // thread-in-group 0..3

    const int m0 = blockIdx.y * TM;
    const int n0 = blockIdx.x * TN;

    // loader: 2 threads per row, 8 consecutive k each
    const int lrow = tid >> 1;
    const int lkq  = (tid & 1) * 8;

    float acc[4][4][4];
#pragma unroll
    for (int mi = 0; mi < 4; mi++)
#pragma unroll
        for (int ni = 0; ni < 4; ni++)
#pragma unroll
            for (int e = 0; e < 4; e++) acc[mi][ni][e] = 0.f;

    const float* Ap = A + (size_t)(m0 + lrow) * lda + lkq;
    const float* Wp = W + (size_t)(n0 + lrow) * ldw + lkq;

    float4 fa0, fa1, fw0, fw1;
    // prologue fetch chunk 0
    fa0 = *(const float4*)(Ap);     fa1 = *(const float4*)(Ap + 4);
    fw0 = *(const float4*)(Wp);     fw1 = *(const float4*)(Wp + 4);

    const int nchunks = K / TKC;
    for (int ch = 0; ch < nchunks; ch++) {
        const int buf = ch & 1;
        // store fetched regs -> smem (tf32 convert)
        {
            uint32_t* as = As[buf] + lrow * SSTR + lkq;
            as[0] = f2tf32(fa0.x); as[1] = f2tf32(fa0.y);
            as[2] = f2tf32(fa0.z); as[3] = f2tf32(fa0.w);
            as[4] = f2tf32(fa1.x); as[5] = f2tf32(fa1.y);
            as[6] = f2tf32(fa1.z); as[7] = f2tf32(fa1.w);
            uint32_t* ws = Ws[buf] + lrow * SSTR + lkq;
            ws[0] = f2tf32(fw0.x); ws[1] = f2tf32(fw0.y);
            ws[2] = f2tf32(fw0.z); ws[3] = f2tf32(fw0.w);
            ws[4] = f2tf32(fw1.x); ws[5] = f2tf32(fw1.y);
            ws[6] = f2tf32(fw1.z); ws[7] = f2tf32(fw1.w);
        }
        __syncthreads();

        // fetch next chunk into regs (overlaps with mma below)
        if (ch + 1 < nchunks) {
            const float* Ap2 = Ap + (ch + 1) * TKC;
            const float* Wp2 = Wp + (ch + 1) * TKC;
            fa0 = *(const float4*)(Ap2);  fa1 = *(const float4*)(Ap2 + 4);
            fw0 = *(const float4*)(Wp2);  fw1 = *(const float4*)(Wp2 + 4);
        }

        // compute: 2 k-steps of m16n8k8
#pragma unroll
        for (int ks = 0; ks < TKC; ks += 8) {
            uint32_t afr[4][4], bfr[4][2];
#pragma unroll
            for (int mi = 0; mi < 4; mi++) {
                const uint32_t* r0 = As[buf] + (wm + mi * 16 + g) * SSTR + ks + tg;
                const uint32_t* r1 = As[buf] + (wm + mi * 16 + 8 + g) * SSTR + ks + tg;
                afr[mi][0] = r0[0];
                afr[mi][1] = r1[0];
                afr[mi][2] = r0[4];
                afr[mi][3] = r1[4];
            }
#pragma unroll
            for (int ni = 0; ni < 4; ni++) {
                const uint32_t* rb = Ws[buf] + (wn + ni * 8 + g) * SSTR + ks + tg;
                bfr[ni][0] = rb[0];
                bfr[ni][1] = rb[4];
            }
#pragma unroll
            for (int mi = 0; mi < 4; mi++)
#pragma unroll
                for (int ni = 0; ni < 4; ni++)
                    MMA_TF32(acc[mi][ni], afr[mi], bfr[ni]);
        }
        __syncthreads();
    }

    // epilogue: c0,c1 -> (row g, cols 2tg,2tg+1); c2,c3 -> row g+8
#pragma unroll
    for (int mi = 0; mi < 4; mi++) {
#pragma unroll
        for (int ni = 0; ni < 4; ni++) {
            const int col = n0 + wn + ni * 8 + 2 * tg;
            const float bx = bias ? bias[col]     : 0.f;
            const float by = bias ? bias[col + 1] : 0.f;
            const int r0 = m0 + wm + mi * 16 + g;
            float2 v0 = make_float2(acc[mi][ni][0] + bx, acc[mi][ni][1] + by);
            float2 v1 = make_float2(acc[mi][ni][2] + bx, acc[mi][ni][3] + by);
            *(float2*)&C[(size_t)r0 * N + col]       = v0;
            *(float2*)&C[(size_t)(r0 + 8) * N + col] = v1;
        }
    }
}

// ---------------- prep kernels ----------------
__global__ void k_reorder_v(const float* __restrict__ Wih, float* __restrict__ Wrev)
{
    int idx = blockIdx.x * 256 + threadIdx.x;      // G4*HV
    int j = idx >> 10, k = idx & 1023;
    int i = j >> 2, g = j & 3;
    Wrev[idx] = Wih[(size_t)(g * HI + i) * (HT + HV) + k];
}
__global__ void k_reorder_s(const float* __restrict__ Wih, float* __restrict__ Wres)
{
    int idx = blockIdx.x * 256 + threadIdx.x;      // G4*HT
    int j = idx >> 9, k = idx & 511;
    int i = j >> 2, g = j & 3;
    Wres[idx] = Wih[(size_t)(g * HI + i) * (HT + HV) + HV + k];
}
__global__ void k_wcat2(const float* __restrict__ WR, const float* __restrict__ Whh,
                        float* __restrict__ Wc)
{
    int idx = blockIdx.x * 256 + threadIdx.x;      // NCAT*HI
    int r = idx >> 9, k = idx & 511;
    if (r < HI) Wc[idx] = WR[(size_t)r * HI + k];
    else {
        int j = r - HI, i = j >> 2, g = j & 3;
        Wc[idx] = Whh[(size_t)(g * HI + i) * HI + k];
    }
}
__global__ void k_biasg(const float* __restrict__ bih, const float* __restrict__ bhh,
                        float* __restrict__ bg)
{
    int j = blockIdx.x * 256 + threadIdx.x;
    if (j < G4) {
        int i = j >> 2, g = j & 3;
        bg[j] = bih[g * HI + i] + bhh[g * HI + i];
    }
}
__global__ void k_tobf16(const float* __restrict__ src, __nv_bfloat16* __restrict__ dst,
                         size_t n)
{
    size_t idx = (size_t)blockIdx.x * 256 + threadIdx.x;
    if (idx < n) dst[idx] = __float2bfloat16(src[idx]);
}

// ---------------- persistent scan kernel ----------------
__global__ __launch_bounds__(TPB) void k_scan(
    const float* __restrict__ bR,
    const float* __restrict__ Ww,
    const float* __restrict__ bw,
    float* __restrict__ out)
{
    __shared__ float  sm[4608];       // stage-unioned
    __shared__ float2 ttab[520];      // tanh LUT over [-4,4], step 1/64
    __shared__ float  ww_s[512];
    __shared__ float  bR_s[512];

    const int bx  = blockIdx.x;
    const int tid = threadIdx.x;

    float* Sproj = g_scratch + OFF_SPROJ;
    float* Vproj = g_scratch + OFF_VPROJ;
    float* Xgv   = g_scratch + OFF_XGV;
    float* Wcat2 = g_scratch + OFF_WCAT2;
    float* hbuf  = g_scratch + OFF_HB;
    float* cbuf  = g_scratch + OFF_CB;
    float* pbuf  = g_scratch + OFF_PBUF;
    float* eb    = g_scratch + OFF_EB;
    const __nv_bfloat16* Pb = (const __nv_bfloat16*)(g_scratch + OFF_PB);

    for (int i = tid; i < 520; i += TPB) {
        float x0 = -4.f + (float)i * (1.f / 64.f);
        float v0 = tanhf(x0);
        float v1 = tanhf(x0 + (1.f / 64.f));
        ttab[i] = make_float2(v0, v1 - v0);
    }
    for (int i = tid; i < 512; i += TPB) { ww_s[i] = Ww[i]; bR_s[i] = bR[i]; }
    for (int idx = bx * TPB + tid; idx < (int)(SZ_HB + SZ_CB); idx += GRID * TPB) {
        if (idx < (int)SZ_HB) hbuf[idx] = 0.f;
        else                  cbuf[idx - (int)SZ_HB] = 0.f;
    }
    const float bw0 = bw[0];
    grid_sync();

    for (int t = 0; t < TT; t++) {
        const float* hp = hbuf + (size_t)(t & 1) * (BB * HI);
        float*       hn = hbuf + (size_t)((t + 1) & 1) * (BB * HI);

        // ========= stage A: pbuf[sl][b][col] = hp @ Wcat2^T, pipelined items =====
        {
            float* Hs  = sm;             // [32][68] k x b
            float* Wsh = sm + 32 * 68;   // [32][68] k x col
            const int tx4 = (tid & 15) * 4;
            const int ty4 = (tid >> 4) * 4;

            float hreg[8], wreg[8];
            // fetch item 0
            {
                const int item = bx * IPB;
                const int col0 = (item >> 4) * 64;
                const int k0   = (item & 15) * 32;
                int e = tid;
#pragma unroll
                for (int r = 0; r < 8; r++, e += TPB) {
                    hreg[r] = hp[(size_t)(e >> 5) * HI + k0 + (e & 31)];
                    wreg[r] = Wcat2[(size_t)(col0 + (e >> 5)) * HI + k0 + (e & 31)];
                }
            }

#pragma unroll
            for (int q = 0; q < IPB; q++) {
                const int item = bx * IPB + q;
                const int nt   = item >> 4;
                const int sl   = item & 15;
                const int col0 = nt * 64;

                __syncthreads();   // previous compute done reading smem
                {
                    int e = tid;
#pragma unroll
                    for (int r = 0; r < 8; r++, e += TPB) {
                        Hs [(e & 31) * 68 + (e >> 5)] = hreg[r];
                        Wsh[(e & 31) * 68 + (e >> 5)] = wreg[r];
                    }
                }
                __syncthreads();

                // prefetch next item while computing this one
                if (q + 1 < IPB) {
                    const int item2 = item + 1;
                    const int col2  = (item2 >> 4) * 64;
                    const int k2    = (item2 & 15) * 32;
                    int e = tid;
#pragma unroll
                    for (int r = 0; r < 8; r++, e += TPB) {
                        hreg[r] = hp[(size_t)(e >> 5) * HI + k2 + (e & 31)];
                        wreg[r] = Wcat2[(size_t)(col2 + (e >> 5)) * HI + k2 + (e & 31)];
                    }
                }

                float acc[4][4];
#pragma unroll
                for (int i = 0; i < 4; i++)
#pragma unroll
                    for (int j = 0; j < 4; j++) acc[i][j] = 0.f;
#pragma unroll
                for (int kk = 0; kk < 32; kk++) {
                    float4 a = *(const float4*)&Hs[kk * 68 + ty4];
                    float4 w = *(const float4*)&Wsh[kk * 68 + tx4];
                    float av[4] = {a.x, a.y, a.z, a.w};
                    float wv[4] = {w.x, w.y, w.z, w.w};
#pragma unroll
                    for (int i = 0; i < 4; i++)
#pragma unroll
                        for (int j = 0; j < 4; j++) acc[i][j] += av[i] * wv[j];
                }
#pragma unroll
                for (int i = 0; i < 4; i++) {
                    float4 v = make_float4(acc[i][0], acc[i][1], acc[i][2], acc[i][3]);
                    *(float4*)&pbuf[((size_t)sl * BB + ty4 + i) * NCAT + col0 + tx4] = v;
                }
            }
        }
        grid_sync();

        // ========= stage B: x-reduce + LUT-tanh attention -> eb = exp(beta) =====
        {
            const int b  = bx >> 1;
            const int nh = bx & 1;
            float* xrow = sm;

            for (int i = tid; i < HI; i += TPB) {
                float v = bR_s[i] + Vproj[((size_t)b * TT + t) * HI + i];
#pragma unroll
                for (int sl = 0; sl < NSLAB; sl++)
                    v += pbuf[((size_t)sl * BB + b) * NCAT + i];
                xrow[i] = v;
            }
            __syncthreads();

            const int w    = tid >> 5;
            const int lane = tid & 31;
#pragma unroll
            for (int q = 0; q < 5; q++) {
                const int n = nh * 40 + w * 5 + q;
                const float* Sp = Sproj + ((size_t)b * NN + n) * HI;
                float acc = 0.f;
#pragma unroll 4
                for (int i = lane; i < HI; i += 32) {
                    float x = Sp[i] + xrow[i];
                    float p = fminf(fmaxf(x, -4.f), 4.f) * 64.f + 256.f;
                    int   ix = (int)p;
                    float fr = p - (float)ix;
                    float2 en = ttab[ix];
                    acc += fmaf(en.y, fr, en.x) * ww_s[i];
                }
#pragma unroll
                for (int o = 16; o > 0; o >>= 1)
                    acc += __shfl_down_sync(0xffffffffu, acc, o);
                if (lane == 0) eb[n * BB + b] = __expf(acc + bw0);
            }
        }
        grid_sync();

        // ========= stage C: softmax + gate assembly (P-weighted) + LSTM =========
        {
            const int b = bx >> 1;
            const int h = bx & 1;
            float* al = sm;

            if (tid < NN) {
                const float* er = eb + tid * BB;
                float s = 0.f;
#pragma unroll
                for (int bb = 0; bb < BB; bb += 4) {
                    float4 v = *(const float4*)&er[bb];
                    s += v.x + v.y + v.z + v.w;
                }
                al[tid] = er[b] / s;
            }
            __syncthreads();

            const int j  = h * 1024 + tid * 4;
            const int ii = h * 256 + tid;

            float4 acc = *(const float4*)&Xgv[((size_t)b * TT + t) * G4 + j];
#pragma unroll
            for (int sl = 0; sl < NSLAB; sl++) {
                float4 p = *(const float4*)&pbuf[((size_t)sl * BB + b) * NCAT + HI + j];
                acc.x += p.x; acc.y += p.y; acc.z += p.z; acc.w += p.w;
            }

            const __nv_bfloat16* Pp = Pb + (size_t)b * NN * G4 + j;
#pragma unroll 16
            for (int n = 0; n < NN; n++) {
                float a = al[n];
                uint2 raw = *(const uint2*)(Pp + (size_t)n * G4);
                float2 lo = __bfloat1622float2(*(const __nv_bfloat162*)&raw.x);
                float2 hi = __bfloat1622float2(*(const __nv_bfloat162*)&raw.y);
                acc.x = fmaf(a, lo.x, acc.x);
                acc.y = fmaf(a, lo.y, acc.y);
                acc.z = fmaf(a, hi.x, acc.z);
                acc.w = fmaf(a, hi.y, acc.w);
            }

            const float ig = fast_sig(acc.x);
            const float fg = fast_sig(acc.y);
            const float gg = fast_tanh(acc.z);
            const float og = fast_sig(acc.w);

            const size_t ci = (size_t)b * HI + ii;
            const float cn = fg * cbuf[ci] + ig * gg;
            const float hh = og * fast_tanh(cn);
            cbuf[ci] = cn;
            hn[ci]   = hh;
            out[((size_t)b * TT + t) * HI + ii] = hh;
        }
        grid_sync();
    }
}

// ---------------- host launcher ----------------
extern "C" void kernel_launch(void* const* d_in, const int* in_sizes, int n_in,
                              void* d_out, int out_size)
{
    const float* h_v  = (const float*)d_in[0];
    const float* h_s  = (const float*)d_in[1];
    const float* W_S  = (const float*)d_in[2];
    const float* b_S  = (const float*)d_in[3];
    const float* W_V  = (const float*)d_in[4];
    const float* b_V  = (const float*)d_in[5];
    const float* W_R  = (const float*)d_in[6];
    const float* b_R  = (const float*)d_in[7];
    const float* W_w  = (const float*)d_in[8];
    const float* b_w  = (const float*)d_in[9];
    const float* W_ih = (const float*)d_in[10];
    const float* b_ih = (const float*)d_in[11];
    const float* W_hh = (const float*)d_in[12];
    const float* b_hh = (const float*)d_in[13];
    float* out = (float*)d_out;

    void* base_v = nullptr;
    cudaGetSymbolAddress(&base_v, g_scratch);
    float* base = (float*)base_v;

    float* Sproj = base + OFF_SPROJ;
    float* Vproj = base + OFF_VPROJ;
    float* Xgv   = base + OFF_XGV;
    float* Pf    = base + OFF_PF;
    __nv_bfloat16* Pbf = (__nv_bfloat16*)(base + OFF_PB);
    float* Wrev  = base + OFF_WREV;
    float* Wres  = base + OFF_WRES;
    float* Wcat2 = base + OFF_WCAT2;
    float* biasg = base + OFF_BIASG;

    // prep (weight reorders)
    k_reorder_v<<<(G4 * HV) / 256, 256>>>(W_ih, Wrev);
    k_reorder_s<<<(G4 * HT) / 256, 256>>>(W_ih, Wres);
    k_wcat2<<<(NCAT * HI) / 256, 256>>>(W_R, W_hh, Wcat2);
    k_biasg<<<8, 256>>>(b_ih, b_hh, biasg);

    // hoisted GEMMs on tensor cores (tf32 mma)
    // S_proj: (5120,512) x (512,512)^T + b_S
    gemm_tf32<<<dim3(HI / TN, (BB * NN) / TM), 256>>>(h_s, HT, W_S, HT, b_S,
                                                      Sproj, BB * NN, HI, HT);
    // V_proj: (32768,1024) x (512,1024)^T + b_V
    gemm_tf32<<<dim3(HI / TN, (BB * TT) / TM), 256>>>(h_v, HV, W_V, HV, b_V,
                                                      Vproj, BB * TT, HI, HV);
    // X_gv: (32768,1024) x (2048,1024)^T + biasg   (reordered cols)
    gemm_tf32<<<dim3(G4 / TN, (BB * TT) / TM), 256>>>(h_v, HV, Wrev, HV, biasg,
                                                      Xgv, BB * TT, G4, HV);
    // P: (5120,512) x (2048,512)^T
    gemm_tf32<<<dim3(G4 / TN, (BB * NN) / TM), 256>>>(h_s, HT, Wres, HT, nullptr,
                                                      Pf, BB * NN, G4, HT);
    k_tobf16<<<(int)((SZ_PF + 255) / 256), 256>>>(Pf, Pbf, SZ_PF);

    // the whole sequential scan: ONE kernel, 3 grid barriers per step
    k_scan<<<GRID, TPB>>>(b_R, W_w, b_w, out);

    (void)in_sizes; (void)n_in; (void)out_size;
}